// round 2
// baseline (speedup 1.0000x reference)
#include <cuda_runtime.h>
#include <cstdint>

#define BB 256
#define TT 512
#define CC 128

// Scratch (no allocations allowed): score rows s_t for t=0..510 (~67MB), final tags.
__device__ float g_scores[(TT - 1) * BB * CC];
__device__ int g_final_tag[BB];

// ---------------------------------------------------------------------------
// helpers
// ---------------------------------------------------------------------------
__device__ __forceinline__ unsigned long long packf2(float lo, float hi) {
    return (unsigned long long)__float_as_uint(lo) |
           ((unsigned long long)__float_as_uint(hi) << 32);
}

// packed fp32 add (sm_100a): two IEEE rn adds in one instruction (fma pipe)
__device__ __forceinline__ float2 addx2(float ax, float ay, unsigned long long b) {
    unsigned long long a = packf2(ax, ay);
    unsigned long long r;
    asm("add.rn.f32x2 %0, %1, %2;" : "=l"(r) : "l"(a), "l"(b));
    return make_float2(__uint_as_float((unsigned)r),
                       __uint_as_float((unsigned)(r >> 32)));
}

// order-preserving float -> uint transform (monotone, bijective except +-0)
__device__ __forceinline__ unsigned srt(float f) {
    unsigned u = __float_as_uint(f);
    return u ^ (unsigned)(((int)u >> 31) | 0x80000000);
}

// ---------------------------------------------------------------------------
// Forward: 256 threads per CTA, one CTA per batch. Warp w covers states
// j = 16w..16w+15 in BOTH halves: lanes 0-15 reduce i in [0,64), lanes 16-31
// reduce i in [64,128); halves merged with one shfl_xor. MAX ONLY — argmax is
// recomputed lazily in the backtrack. Score rows streamed to g_scores.
// ---------------------------------------------------------------------------
__global__ __launch_bounds__(2 * CC, 2)
void viterbi_fwd(const float* __restrict__ em,
                 const float* __restrict__ trans,
                 float* __restrict__ out)
{
    __shared__ __align__(16) float s_prev[2][CC];

    const int b    = blockIdx.x;
    const int tid  = threadIdx.x;
    const int w    = tid >> 5;
    const int lane = tid & 31;
    const int sub  = lane >> 4;          // which i-half this lane reduces
    const int j    = w * 16 + (lane & 15);
    const int i0   = sub * 64;

    // Own half-column of trans, packed in pairs for f32x2 adds (64 regs).
    unsigned long long tc2[32];
#pragma unroll
    for (int k = 0; k < 32; ++k)
        tc2[k] = packf2(trans[(i0 + 2 * k) * CC + j],
                        trans[(i0 + 2 * k + 1) * CC + j]);

    const float* emb = em + (size_t)b * TT * CC;
    float cur = emb[j];

    float* sc = g_scores + (size_t)b * CC + j;     // s_t[b][j], stride BB*CC per t
    if (sub == 0) {
        s_prev[0][j] = cur;
        sc[0] = cur;                               // s_0
    }
    __syncthreads();

    int buf = 0;
    for (int t = 1; t < TT; ++t) {
        float emv = emb[t * CC + j];               // covered by phase-1 latency

        const float4* pv = (const float4*)&s_prev[buf][i0];
        float M;
#pragma unroll
        for (int g = 0; g < 8; ++g) {
            float4 p0 = pv[2 * g];
            float4 p1 = pv[2 * g + 1];
            float2 c01 = addx2(p0.x, p0.y, tc2[4 * g + 0]);
            float2 c23 = addx2(p0.z, p0.w, tc2[4 * g + 1]);
            float2 c45 = addx2(p1.x, p1.y, tc2[4 * g + 2]);
            float2 c67 = addx2(p1.z, p1.w, tc2[4 * g + 3]);
            float m = fmaxf(fmaxf(fmaxf(c01.x, c01.y), fmaxf(c23.x, c23.y)),
                            fmaxf(fmaxf(c45.x, c45.y), fmaxf(c67.x, c67.y)));
            M = (g == 0) ? m : fmaxf(M, m);
        }
        // merge the two i-halves (value only)
        float Mo = __shfl_xor_sync(0xffffffffu, M, 16);
        float Mf = fmaxf(M, Mo);
        float c  = Mf + emv;

        buf ^= 1;
        if (sub == 0) {
            s_prev[buf][j] = c;
            if (t < TT - 1)
                sc[(size_t)t * BB * CC] = c;       // s_t (t <= 510)
        }
        cur = c;
        __syncthreads();
    }

    // Final per-batch first-occurrence argmax over s_511 (runs once).
    if (tid == 0) {
        float best = s_prev[buf][0];
        int arg = 0;
#pragma unroll 1
        for (int i = 1; i < CC; ++i) {
            float v = s_prev[buf][i];
            if (v > best) { best = v; arg = i; }
        }
        g_final_tag[b] = arg;
        out[(size_t)BB * TT + b] = best;
    }
}

// ---------------------------------------------------------------------------
// Backtrack with lazy argmax recompute: one warp per batch (8 warps/CTA).
// Per step: v_i = s_u[i] + trans[i][tag] (bit-identical fp32 re-adds), exact
// first-index argmax via sortable-uint redux + ballot. Score rows prefetched
// 8 steps ahead into a static register ring (addresses tag-independent).
// ---------------------------------------------------------------------------
__global__ __launch_bounds__(256)
void viterbi_bt(const float* __restrict__ trans,
                float* __restrict__ out)
{
    extern __shared__ float s_tT[];                // trans transposed, stride 132
    const int tid = threadIdx.x;

    // Stage trans transposed: s_tT[jc*132 + i] = trans[i*CC + jc]
    for (int idx = tid; idx < CC * CC; idx += 256) {
        int i = idx >> 7, jc = idx & 127;
        s_tT[jc * 132 + i] = trans[idx];
    }
    __syncthreads();

    const int wid  = tid >> 5;
    const int lane = tid & 31;
    const int b    = blockIdx.x * 8 + wid;

    int tag = g_final_tag[b];
    if (lane == 0) out[(size_t)b * TT + (TT - 1)] = (float)tag;

    // register ring of score rows: slot r holds s_{510 - (i mod 8 ... )}
    const float* srow = g_scores + (size_t)b * CC + lane * 4;
    float4 ring[8];
#pragma unroll
    for (int r = 0; r < 8; ++r)
        ring[r] = *(const float4*)(srow + (size_t)(TT - 2 - r) * BB * CC);

    for (int ib = 0; ib < 64; ++ib) {
#pragma unroll
        for (int r = 0; r < 8; ++r) {
            int i = ib * 8 + r;
            int u = (TT - 2) - i;                  // 510 .. -1
            if (u >= 0) {
                float4 sc = ring[r];
                int up = u - 8;
                if (up >= 0)
                    ring[r] = *(const float4*)(srow + (size_t)up * BB * CC);

                const float4 tr = *(const float4*)(s_tT + tag * 132 + lane * 4);
                float v0 = sc.x + tr.x;
                float v1 = sc.y + tr.y;
                float v2 = sc.z + tr.z;
                float v3 = sc.w + tr.w;

                float lm = fmaxf(fmaxf(v0, v1), fmaxf(v2, v3));
                unsigned ls = srt(lm);
                unsigned ws = __reduce_max_sync(0xffffffffu, ls);

                unsigned bal = __ballot_sync(0xffffffffu, ls == ws);
                int L = __ffs(bal) - 1;            // first lane holding the max

                int myk = 3;                       // first k within lane
                myk = (v2 == lm) ? 2 : myk;
                myk = (v1 == lm) ? 1 : myk;
                myk = (v0 == lm) ? 0 : myk;
                int kk = __shfl_sync(0xffffffffu, myk, L);

                tag = L * 4 + kk;                  // exact first-occurrence
                if (lane == 0) out[(size_t)b * TT + u] = (float)tag;
            }
        }
    }
}

// Empty kernel: pads the launch period to 5 so ncu (-s 5 -c 1) captures fwd.
__global__ void noopk() {}

extern "C" void kernel_launch(void* const* d_in, const int* in_sizes, int n_in,
                              void* d_out, int out_size)
{
    const float* em    = (const float*)d_in[0];
    const float* trans = (const float*)d_in[1];
    float* out = (float*)d_out;

    const int bt_smem = CC * 132 * sizeof(float);  // 67.6KB
    cudaFuncSetAttribute(viterbi_bt, cudaFuncAttributeMaxDynamicSharedMemorySize,
                         bt_smem);

    viterbi_fwd<<<BB, 2 * CC>>>(em, trans, out);
    viterbi_bt<<<BB / 8, 256, bt_smem>>>(trans, out);
    noopk<<<1, 32>>>();
    noopk<<<1, 32>>>();
    noopk<<<1, 32>>>();
}

// round 3
// speedup vs baseline: 1.1542x; 1.1542x over previous
#include <cuda_runtime.h>
#include <cstdint>

#define BB 256
#define TT 512
#define CC 128

// Scratch (allocations forbidden): score rows s_t, t=0..510 (~67MB) + final tags.
__device__ float g_scores[(TT - 1) * BB * CC];
__device__ int g_final_tag[BB];

// ---------------------------------------------------------------------------
// helpers
// ---------------------------------------------------------------------------
__device__ __forceinline__ unsigned long long packf2(float lo, float hi) {
    return (unsigned long long)__float_as_uint(lo) |
           ((unsigned long long)__float_as_uint(hi) << 32);
}

// packed fp32 add (sm_100a): two IEEE rn adds, one fma-pipe instruction
__device__ __forceinline__ float2 addx2(float ax, float ay, unsigned long long b) {
    unsigned long long a = packf2(ax, ay);
    unsigned long long r;
    asm("add.rn.f32x2 %0, %1, %2;" : "=l"(r) : "l"(a), "l"(b));
    return make_float2(__uint_as_float((unsigned)r),
                       __uint_as_float((unsigned)(r >> 32)));
}

// order-preserving float -> uint transform
__device__ __forceinline__ unsigned srt(float f) {
    unsigned u = __float_as_uint(f);
    return u ^ (unsigned)(((int)u >> 31) | 0x80000000);
}

// ---------------------------------------------------------------------------
// Forward (range [t0,t1)): R1 shape — 128 threads/CTA, thread j owns state j
// and reduces all 128 i's itself. MAX ONLY (argmax recomputed lazily in bt).
// Full trans column in registers as f32x2 pairs; one barrier per step; score
// rows streamed to g_scores so the kernel can be split for profiling.
// ---------------------------------------------------------------------------
__global__ __launch_bounds__(CC, 2)
void viterbi_fwd(const float* __restrict__ em,
                 const float* __restrict__ trans,
                 float* __restrict__ out, int t0, int t1)
{
    __shared__ __align__(16) float s_prev[2][CC];

    const int b = blockIdx.x;
    const int j = threadIdx.x;

    // Own column of trans, packed in adjacent-i pairs (128 regs).
    unsigned long long tc2[64];
#pragma unroll
    for (int k = 0; k < 64; ++k)
        tc2[k] = packf2(__ldg(trans + (2 * k) * CC + j),
                        __ldg(trans + (2 * k + 1) * CC + j));

    const float* emb = em + (size_t)b * TT * CC;
    float* sc = g_scores + (size_t)b * CC + j;       // stride BB*CC per t

    float cur;
    if (t0 == 0) {
        cur = emb[j];
        sc[0] = cur;                                  // s_0
    } else {
        cur = sc[(size_t)(t0 - 1) * BB * CC];         // resume from s_{t0-1}
    }
    s_prev[0][j] = cur;
    __syncthreads();

    int buf = 0;
    const int tb = (t0 == 0) ? 1 : t0;
    for (int t = tb; t < t1; ++t) {
        float emv = __ldg(emb + t * CC + j);

        const float4* pv = (const float4*)s_prev[buf];
        float M;
#pragma unroll
        for (int g = 0; g < 16; ++g) {
            float4 p0 = pv[2 * g];
            float4 p1 = pv[2 * g + 1];
            float2 c01 = addx2(p0.x, p0.y, tc2[4 * g + 0]);
            float2 c23 = addx2(p0.z, p0.w, tc2[4 * g + 1]);
            float2 c45 = addx2(p1.x, p1.y, tc2[4 * g + 2]);
            float2 c67 = addx2(p1.z, p1.w, tc2[4 * g + 3]);
            float m = fmaxf(fmaxf(fmaxf(c01.x, c01.y), fmaxf(c23.x, c23.y)),
                            fmaxf(fmaxf(c45.x, c45.y), fmaxf(c67.x, c67.y)));
            M = g ? fmaxf(M, m) : m;
        }

        cur = M + emv;
        buf ^= 1;
        s_prev[buf][j] = cur;
        if (t < TT - 1)
            sc[(size_t)t * BB * CC] = cur;            // s_t, t <= 510
        __syncthreads();
    }

    // Final per-batch first-occurrence argmax over s_511 (last range only).
    if (t1 == TT && j == 0) {
        float best = s_prev[buf][0];
        int arg = 0;
#pragma unroll 1
        for (int i = 1; i < CC; ++i) {
            float v = s_prev[buf][i];
            if (v > best) { best = v; arg = i; }
        }
        g_final_tag[b] = arg;
        out[(size_t)BB * TT + b] = best;              // final_score[b]
    }
}

// ---------------------------------------------------------------------------
// Backtrack with lazy exact argmax: one warp per batch (8 warps/CTA).
// v_i = s_u[i] + trans[i][tag] (bit-identical fp32 re-adds); exact first-index
// tie-break via sortable-uint reduce_max + ballot. Score rows prefetched 8
// ahead into a register ring (addresses tag-independent).
// ---------------------------------------------------------------------------
__global__ __launch_bounds__(256)
void viterbi_bt(const float* __restrict__ trans,
                float* __restrict__ out)
{
    extern __shared__ float s_tT[];                   // trans^T, stride 132
    const int tid = threadIdx.x;

    for (int idx = tid; idx < CC * CC; idx += 256) {
        int i = idx >> 7, jc = idx & 127;
        s_tT[jc * 132 + i] = trans[idx];
    }
    __syncthreads();

    const int wid  = tid >> 5;
    const int lane = tid & 31;
    const int b    = blockIdx.x * 8 + wid;

    int tag = g_final_tag[b];
    if (lane == 0) out[(size_t)b * TT + (TT - 1)] = (float)tag;

    const float* srow = g_scores + (size_t)b * CC + lane * 4;
    float4 ring[8];
#pragma unroll
    for (int r = 0; r < 8; ++r)
        ring[r] = *(const float4*)(srow + (size_t)(TT - 2 - r) * BB * CC);

    for (int ib = 0; ib < 64; ++ib) {
#pragma unroll
        for (int r = 0; r < 8; ++r) {
            int i = ib * 8 + r;
            int u = (TT - 2) - i;                     // 510 .. -1
            if (u >= 0) {
                float4 scv = ring[r];
                int up = u - 8;
                if (up >= 0)
                    ring[r] = *(const float4*)(srow + (size_t)up * BB * CC);

                const float4 tr = *(const float4*)(s_tT + tag * 132 + lane * 4);
                float v0 = scv.x + tr.x;
                float v1 = scv.y + tr.y;
                float v2 = scv.z + tr.z;
                float v3 = scv.w + tr.w;

                float lm = fmaxf(fmaxf(v0, v1), fmaxf(v2, v3));
                unsigned ls = srt(lm);
                unsigned ws = __reduce_max_sync(0xffffffffu, ls);

                unsigned bal = __ballot_sync(0xffffffffu, ls == ws);
                int L = __ffs(bal) - 1;               // first lane with max

                int myk = 3;
                myk = (v2 == lm) ? 2 : myk;
                myk = (v1 == lm) ? 1 : myk;
                myk = (v0 == lm) ? 0 : myk;
                int kk = __shfl_sync(0xffffffffu, myk, L);

                tag = L * 4 + kk;                     // exact first occurrence
                if (lane == 0) out[(size_t)b * TT + u] = (float)tag;
            }
        }
    }
}

// ---------------------------------------------------------------------------
// 3 launches per call: fwd split in half (profiling: 2/3 of ncu residues hit
// real forward work), then backtrack.
// ---------------------------------------------------------------------------
extern "C" void kernel_launch(void* const* d_in, const int* in_sizes, int n_in,
                              void* d_out, int out_size)
{
    const float* em    = (const float*)d_in[0];
    const float* trans = (const float*)d_in[1];
    float* out = (float*)d_out;

    const int bt_smem = CC * 132 * sizeof(float);     // 67.6KB
    cudaFuncSetAttribute(viterbi_bt, cudaFuncAttributeMaxDynamicSharedMemorySize,
                         bt_smem);

    viterbi_fwd<<<BB, CC>>>(em, trans, out, 0, TT / 2);
    viterbi_fwd<<<BB, CC>>>(em, trans, out, TT / 2, TT);
    viterbi_bt<<<BB / 8, 256, bt_smem>>>(trans, out);
}